// round 13
// baseline (speedup 1.0000x reference)
#include <cuda_runtime.h>
#include <cstdint>
#include <cstddef>

#define NPTS   16384
#define MN     512
#define DM     256
#define KNNK   128
#define TWO_PI 6.28318530717958647692f

__device__ float g_Wd_hi[DM*DM];
__device__ float g_Wd_lo[DM*DM];
__device__ float g_Wp_hi[DM*DM];
__device__ float g_Wp_lo[DM*DM];
__device__ int   g_knn[MN*KNNK];

static __device__ __forceinline__ unsigned f2tf(float x){
    unsigned u; asm("cvt.rna.tf32.f32 %0, %1;" : "=r"(u) : "f"(x)); return u;
}
static __device__ __forceinline__ float tfr(float x){ return __uint_as_float(f2tf(x)); }

static __device__ __forceinline__ float angle3(float vx,float vy,float vz,
                                               float nx,float ny,float nz){
    float cx = vy*nz - vz*ny;
    float cy = vz*nx - vx*nz;
    float cz = vx*ny - vy*nx;
    float s  = sqrtf(cx*cx + cy*cy + cz*cz);
    float d  = vx*nx + vy*ny + vz*nz;
    return atan2f(s, d);
}
static __device__ __forceinline__ void mma8(float* c, const unsigned* a, const unsigned* b){
    asm volatile("mma.sync.aligned.m16n8k8.row.col.f32.tf32.tf32.f32 "
        "{%0,%1,%2,%3}, {%4,%5,%6,%7}, {%8,%9}, {%0,%1,%2,%3};"
        : "+f"(c[0]), "+f"(c[1]), "+f"(c[2]), "+f"(c[3])
        : "r"(a[0]), "r"(a[1]), "r"(a[2]), "r"(a[3]), "r"(b[0]), "r"(b[1]));
}

#define SST 68
#define SEH_OFF 0
#define SEL_OFF (SEH_OFF + 128*SST)
#define SWH_OFF (SEL_OFF + 128*SST)
#define SWL_OFF (SWH_OFF + 256*SST)
#define SF_OFF  (SWL_OFF + 256*SST)
#define ST_OFF  (SF_OFF + 512)
#define SR_OFF  (ST_OFF + 128)
#define SMEM_FLOATS (SR_OFF + 1024)
#define SMEM_BYTES (SMEM_FLOATS * 4)

__global__ void prep_kernel(const float* __restrict__ Wd, const float* __restrict__ Wp){
    int i = blockIdx.x * blockDim.x + threadIdx.x;
    if (i < DM*DM){
        float wd = Wd[i];
        float wdh = tfr(wd);
        g_Wd_hi[i] = wdh;
        g_Wd_lo[i] = tfr(wd - wdh);
        float wp = Wp[i];
        float wph = tfr(wp);
        g_Wp_hi[i] = wph;
        g_Wp_lo[i] = tfr(wp - wph);
    }
}

__global__ void __launch_bounds__(256) knn_kernel(const float* __restrict__ pts,
                                                  const float* __restrict__ nds){
    int m = blockIdx.x, tid = threadIdx.x;
    __shared__ int scnt;
    __shared__ int pos;
    float nx = nds[3*m], ny = nds[3*m+1], nz = nds[3*m+2];
    float sqn = nx*nx + ny*ny + nz*nz;
    float v[64];
    #pragma unroll 4
    for (int s = 0; s < 64; s++){
        int i = s*256 + tid;
        float px = pts[3*i], py = pts[3*i+1], pz = pts[3*i+2];
        float sqp = px*px + py*py + pz*pz;
        float dot = nx*px + ny*py + nz*pz;
        v[s] = fmaxf((sqn + sqp) - 2.0f*dot, 0.f);
    }
    unsigned lo = 0u, hi = 0x7f800000u;
    while (lo < hi){
        unsigned mid = (lo + hi) >> 1;
        float fm = __uint_as_float(mid);
        if (tid == 0) scnt = 0;
        __syncthreads();
        int c = 0;
        #pragma unroll
        for (int s = 0; s < 64; s++) c += (v[s] <= fm) ? 1 : 0;
        c = (int)__reduce_add_sync(0xffffffffu, (unsigned)c);
        if ((tid & 31) == 0) atomicAdd(&scnt, c);
        __syncthreads();
        int total = scnt;
        __syncthreads();
        if (total >= KNNK) hi = mid; else lo = mid + 1;
    }
    float thr = __uint_as_float(lo);
    if (tid == 0) pos = 0;
    __syncthreads();
    for (int s = 0; s < 64; s++){
        if (v[s] < thr){
            int p = atomicAdd(&pos, 1);
            g_knn[m*KNNK + p] = s*256 + tid;
        }
    }
    __syncthreads();
    for (int s = 0; s < 64; s++){
        if (v[s] == thr){
            int p = atomicAdd(&pos, 1);
            if (p < KNNK) g_knn[m*KNNK + p] = s*256 + tid;
        }
    }
}

template<class EGen>
static __device__ __forceinline__ void gemm3(float* sm,
                                             const float* __restrict__ Wh,
                                             const float* __restrict__ Wl,
                                             float acc[2][8][4], int tid, EGen egen){
    float* sEh = sm + SEH_OFF;
    float* sEl = sm + SEL_OFF;
    float* sWh = sm + SWH_OFF;
    float* sWl = sm + SWL_OFF;
    int wid = tid >> 5, lane = tid & 31;
    int wm = wid >> 2, wn = wid & 3;
    int lq = lane >> 2, lr = lane & 3;
    int r0 = wm * 32, c0 = wn * 64;
    for (int kc = 0; kc < 4; kc++){
        __syncthreads();
        for (int q = tid; q < 4096; q += 512){
            int c = q >> 4, kk = (q & 15) * 4;
            *(float4*)(sWh + c*SST + kk) = *(const float4*)(Wh + c*DM + kc*64 + kk);
            *(float4*)(sWl + c*SST + kk) = *(const float4*)(Wl + c*DM + kc*64 + kk);
        }
        for (int e = tid; e < 128*64; e += 512){
            int row = e >> 6, col = e & 63;
            float val = egen(row, kc*64 + col);
            float h = tfr(val);
            sEh[row*SST + col] = h;
            sEl[row*SST + col] = tfr(val - h);
        }
        __syncthreads();
        #pragma unroll
        for (int k8 = 0; k8 < 8; k8++){
            int kk = k8 * 8;
            unsigned ah[2][4], al[2][4];
            {
                const float* ph = sEh + (r0 + lq)*SST + kk + lr;
                const float* pl = sEl + (r0 + lq)*SST + kk + lr;
                #pragma unroll
                for (int mt = 0; mt < 2; mt++){
                    const float* qh = ph + mt*16*SST;
                    const float* ql = pl + mt*16*SST;
                    ah[mt][0] = __float_as_uint(qh[0]);
                    ah[mt][1] = __float_as_uint(qh[8*SST]);
                    ah[mt][2] = __float_as_uint(qh[4]);
                    ah[mt][3] = __float_as_uint(qh[8*SST + 4]);
                    al[mt][0] = __float_as_uint(ql[0]);
                    al[mt][1] = __float_as_uint(ql[8*SST]);
                    al[mt][2] = __float_as_uint(ql[4]);
                    al[mt][3] = __float_as_uint(ql[8*SST + 4]);
                }
            }
            #pragma unroll
            for (int nt = 0; nt < 8; nt++){
                unsigned bh[2], bl[2];
                const float* ph = sWh + (c0 + nt*8 + lq)*SST + kk + lr;
                const float* pl = sWl + (c0 + nt*8 + lq)*SST + kk + lr;
                bh[0] = __float_as_uint(ph[0]);
                bh[1] = __float_as_uint(ph[4]);
                bl[0] = __float_as_uint(pl[0]);
                bl[1] = __float_as_uint(pl[4]);
                #pragma unroll
                for (int mt = 0; mt < 2; mt++){
                    mma8(acc[mt][nt], ah[mt], bh);
                    mma8(acc[mt][nt], al[mt], bh);
                    mma8(acc[mt][nt], ah[mt], bl);
                }
            }
        }
    }
}

__global__ void __launch_bounds__(512, 1) glo_kernel(const float* __restrict__ nds,
                                                     const float* __restrict__ nn,
                                                     const float* __restrict__ bd,
                                                     float* __restrict__ out){
    extern __shared__ float sm[];
    float* sF = sm + SF_OFF;
    float* sT = sm + ST_OFF;
    int tid = threadIdx.x;
    int rowbase = blockIdx.x * 128;

    if (tid < 128) sT[tid] = exp2f(-(float)tid * 0.10381025296511650f);
    if (tid < 128){
        int gr = rowbase + tid;
        int i = gr >> 9, j = gr & 511;
        float ix = nds[3*i], iy = nds[3*i+1], iz = nds[3*i+2];
        float jx = nds[3*j], jy = nds[3*j+1], jz = nds[3*j+2];
        float dx = ix - jx, dy = iy - jy, dz = iz - jz;
        float dist = sqrtf(dx*dx + dy*dy + dz*dz) * TWO_PI;
        float ax = nn[3*i], ay = nn[3*i+1], az = nn[3*i+2];
        sF[2*tid]   = dist;
        // DIAGONAL FIX: reference's jnp.sum yields +0 for the i==j dot product
        // (reduce init +0; (+0)+(-0)=+0) so arctan2(+0,+0)=0. Our FMA chain can
        // produce -0 (when all normal components are negative) -> atan2=pi.
        // Force the reference's value exactly.
        sF[2*tid+1] = (i == j) ? 0.0f : angle3(dx, dy, dz, ax, ay, az);
    }
    __syncthreads();

    float acc[2][8][4];
    #pragma unroll
    for (int mt = 0; mt < 2; mt++)
        #pragma unroll
        for (int nt = 0; nt < 8; nt++)
            #pragma unroll
            for (int q = 0; q < 4; q++) acc[mt][nt][q] = 0.f;

    gemm3(sm, g_Wd_hi, g_Wd_lo, acc, tid,
        [&](int row, int k) -> float {
            float w = sT[k >> 1];
            float d = sF[2*row], a = sF[2*row+1];
            float x1 = d * w, x2 = a * w;
            return (k & 1) ? (cosf(x1) + cosf(x2)) : (sinf(x1) + sinf(x2));
        });

    int wid = tid >> 5, lane = tid & 31;
    int wm = wid >> 2, wn = wid & 3;
    int lq = lane >> 2, lr = lane & 3;
    #pragma unroll
    for (int mt = 0; mt < 2; mt++){
        #pragma unroll
        for (int nt = 0; nt < 8; nt++){
            int col = wn*64 + nt*8 + 2*lr;
            float b0 = 2.f * bd[col];
            float b1 = 2.f * bd[col+1];
            size_t r1 = (size_t)(rowbase + wm*32 + mt*16 + lq) * DM + col;
            size_t r2 = r1 + (size_t)8 * DM;
            float2 v1 = make_float2(acc[mt][nt][0] + b0, acc[mt][nt][1] + b1);
            float2 v2 = make_float2(acc[mt][nt][2] + b0, acc[mt][nt][3] + b1);
            *(float2*)(out + r1) = v1;
            *(float2*)(out + r2) = v2;
        }
    }
}

__global__ void __launch_bounds__(512, 1) loc_kernel(const float* __restrict__ pts,
                                                     const float* __restrict__ nds,
                                                     const float* __restrict__ pn,
                                                     const float* __restrict__ nn,
                                                     const float* __restrict__ bp,
                                                     float* __restrict__ out){
    extern __shared__ float sm[];
    float* sF = sm + SF_OFF;
    float* sT = sm + ST_OFF;
    float* sR = sm + SR_OFF;
    int tid = threadIdx.x;
    int m = blockIdx.x;

    if (tid < 32) sT[tid] = exp2f(-(float)tid * 0.41524101186046600f);
    if (tid < 128){
        int idx = g_knn[m*KNNK + tid];
        float cx = nds[3*m], cy = nds[3*m+1], cz = nds[3*m+2];
        float ax = nn[3*m],  ay = nn[3*m+1],  az = nn[3*m+2];
        float px = pts[3*idx], py = pts[3*idx+1], pz = pts[3*idx+2];
        float qx = pn[3*idx],  qy = pn[3*idx+1],  qz = pn[3*idx+2];
        float vx = px - cx, vy = py - cy, vz = pz - cz;
        sF[4*tid+0] = sqrtf(vx*vx + vy*vy + vz*vz) * TWO_PI;
        sF[4*tid+1] = angle3( vx,  vy,  vz, ax, ay, az);
        sF[4*tid+2] = angle3(-vx, -vy, -vz, qx, qy, qz);
        sF[4*tid+3] = angle3( ax,  ay,  az, qx, qy, qz);
    }
    __syncthreads();

    float acc[2][8][4];
    #pragma unroll
    for (int mt = 0; mt < 2; mt++)
        #pragma unroll
        for (int nt = 0; nt < 8; nt++)
            #pragma unroll
            for (int q = 0; q < 4; q++) acc[mt][nt][q] = 0.f;

    gemm3(sm, g_Wp_hi, g_Wp_lo, acc, tid,
        [&](int row, int k) -> float {
            float w = sT[(k & 63) >> 1];
            float s = sF[4*row + (k >> 6)];
            float x = s * w;
            return (k & 1) ? cosf(x) : sinf(x);
        });

    int wid = tid >> 5, lane = tid & 31;
    int wm = wid >> 2, wn = wid & 3;
    int lq = lane >> 2, lr = lane & 3;
    #pragma unroll
    for (int nt = 0; nt < 8; nt++){
        float em = fmaxf(fmaxf(acc[0][nt][0], acc[0][nt][2]),
                         fmaxf(acc[1][nt][0], acc[1][nt][2]));
        float om = fmaxf(fmaxf(acc[0][nt][1], acc[0][nt][3]),
                         fmaxf(acc[1][nt][1], acc[1][nt][3]));
        #pragma unroll
        for (int off = 4; off <= 16; off <<= 1){
            em = fmaxf(em, __shfl_xor_sync(0xffffffffu, em, off));
            om = fmaxf(om, __shfl_xor_sync(0xffffffffu, om, off));
        }
        if (lq == 0){
            sR[wm*256 + wn*64 + nt*8 + 2*lr]     = em;
            sR[wm*256 + wn*64 + nt*8 + 2*lr + 1] = om;
        }
    }
    __syncthreads();
    if (tid < 256){
        float mx = fmaxf(fmaxf(sR[tid], sR[256 + tid]),
                         fmaxf(sR[512 + tid], sR[768 + tid]));
        out[(size_t)MN*MN*DM + (size_t)m*DM + tid] = mx + bp[tid];
    }
}

extern "C" void kernel_launch(void* const* d_in, const int* in_sizes, int n_in,
                              void* d_out, int out_size){
    const float* pts   = (const float*)d_in[0];
    const float* nds   = (const float*)d_in[1];
    const float* pnorm = (const float*)d_in[2];
    const float* nnorm = (const float*)d_in[3];
    const float* Wd    = (const float*)d_in[4];
    const float* bd    = (const float*)d_in[5];
    const float* Wp    = (const float*)d_in[6];
    const float* bp    = (const float*)d_in[7];
    float* out = (float*)d_out;

    cudaFuncSetAttribute(glo_kernel, cudaFuncAttributeMaxDynamicSharedMemorySize, SMEM_BYTES);
    cudaFuncSetAttribute(loc_kernel, cudaFuncAttributeMaxDynamicSharedMemorySize, SMEM_BYTES);

    prep_kernel<<<(DM*DM + 255)/256, 256>>>(Wd, Wp);
    knn_kernel<<<MN, 256>>>(pts, nds);
    glo_kernel<<<(MN*MN)/128, 512, SMEM_BYTES>>>(nds, nnorm, bd, out);
    loc_kernel<<<MN, 512, SMEM_BYTES>>>(pts, nds, pnorm, nnorm, bp, out);
}

// round 14
// speedup vs baseline: 2.5467x; 2.5467x over previous
#include <cuda_runtime.h>
#include <cstdint>
#include <cstddef>

#define NPTS   16384
#define MN     512
#define DM     256
#define KNNK   128
#define TWO_PI 6.28318530717958647692f

__device__ float g_Wd[DM*DM];   // tf32-rounded
__device__ float g_Wp[DM*DM];   // tf32-rounded
__device__ int   g_knn[MN*KNNK];

static __device__ __forceinline__ unsigned f2tf(float x){
    unsigned u; asm("cvt.rna.tf32.f32 %0, %1;" : "=r"(u) : "f"(x)); return u;
}
static __device__ __forceinline__ float tfr(float x){ return __uint_as_float(f2tf(x)); }

// reduce to [-pi,pi] with 2-term 2*pi so MUFU sin/cos stays accurate
static __device__ __forceinline__ float redang(float x){
    float k = rintf(x * 0.15915494309189535f);
    float r = fmaf(k, -6.28318548202514648f, x);
    return fmaf(k, 1.74845560074738e-07f, r);
}
static __device__ __forceinline__ float angle3(float vx,float vy,float vz,
                                               float nx,float ny,float nz){
    float cx = vy*nz - vz*ny;
    float cy = vz*nx - vx*nz;
    float cz = vx*ny - vy*nx;
    float s  = sqrtf(cx*cx + cy*cy + cz*cz);
    float d  = vx*nx + vy*ny + vz*nz;
    return atan2f(s, d);
}
static __device__ __forceinline__ void mma8(float* c, const unsigned* a, const unsigned* b){
    asm volatile("mma.sync.aligned.m16n8k8.row.col.f32.tf32.tf32.f32 "
        "{%0,%1,%2,%3}, {%4,%5,%6,%7}, {%8,%9}, {%0,%1,%2,%3};"
        : "+f"(c[0]), "+f"(c[1]), "+f"(c[2]), "+f"(c[3])
        : "r"(a[0]), "r"(a[1]), "r"(a[2]), "r"(a[3]), "r"(b[0]), "r"(b[1]));
}

// ---- smem layout (floats); stride 68 (68%32==4 -> conflict-free frags) ----
// double-buffered E (128x64 chunk) and W (256x64 chunk)
#define SST 68
#define SE0_OFF 0
#define SE1_OFF (128*SST)              // 8704
#define SW0_OFF (2*128*SST)            // 17408
#define SW1_OFF (SW0_OFF + 256*SST)    // 34816
#define SF_OFF  (SW0_OFF + 2*256*SST)  // 52224
#define ST_OFF  (SF_OFF + 512)         // 52736
#define SR_OFF  (ST_OFF + 128)         // 52864
#define SMEM_FLOATS (SR_OFF + 1024)    // 53888
#define SMEM_BYTES (SMEM_FLOATS * 4)   // 215552

__global__ void prep_kernel(const float* __restrict__ Wd, const float* __restrict__ Wp){
    int i = blockIdx.x * blockDim.x + threadIdx.x;
    if (i < DM*DM){
        g_Wd[i] = tfr(Wd[i]);
        g_Wp[i] = tfr(Wp[i]);
    }
}

__global__ void __launch_bounds__(256) knn_kernel(const float* __restrict__ pts,
                                                  const float* __restrict__ nds){
    int m = blockIdx.x, tid = threadIdx.x;
    __shared__ int scnt;
    __shared__ int pos;
    float nx = nds[3*m], ny = nds[3*m+1], nz = nds[3*m+2];
    float sqn = nx*nx + ny*ny + nz*nz;
    float v[64];
    #pragma unroll 4
    for (int s = 0; s < 64; s++){
        int i = s*256 + tid;
        float px = pts[3*i], py = pts[3*i+1], pz = pts[3*i+2];
        float sqp = px*px + py*py + pz*pz;
        float dot = nx*px + ny*py + nz*pz;
        v[s] = fmaxf((sqn + sqp) - 2.0f*dot, 0.f);
    }
    unsigned lo = 0u, hi = 0x7f800000u;
    while (lo < hi){
        unsigned mid = (lo + hi) >> 1;
        float fm = __uint_as_float(mid);
        if (tid == 0) scnt = 0;
        __syncthreads();
        int c = 0;
        #pragma unroll
        for (int s = 0; s < 64; s++) c += (v[s] <= fm) ? 1 : 0;
        c = (int)__reduce_add_sync(0xffffffffu, (unsigned)c);
        if ((tid & 31) == 0) atomicAdd(&scnt, c);
        __syncthreads();
        int total = scnt;
        __syncthreads();
        if (total >= KNNK) hi = mid; else lo = mid + 1;
    }
    float thr = __uint_as_float(lo);
    if (tid == 0) pos = 0;
    __syncthreads();
    for (int s = 0; s < 64; s++){
        if (v[s] < thr){
            int p = atomicAdd(&pos, 1);
            g_knn[m*KNNK + p] = s*256 + tid;
        }
    }
    __syncthreads();
    for (int s = 0; s < 64; s++){
        if (v[s] == thr){
            int p = atomicAdd(&pos, 1);
            if (p < KNNK) g_knn[m*KNNK + p] = s*256 + tid;
        }
    }
}

// ---- pure-TF32 GEMM, double-buffered W+E chunks ----
// egen(row, kc, t2) -> float2 {even_col_val, odd_col_val} for cols (2*t2, 2*t2+1)
template<class EGen>
static __device__ __forceinline__ void gemm1(float* sm,
                                             const float* __restrict__ Wg,
                                             float acc[2][8][4], int tid, EGen egen){
    int wid = tid >> 5, lane = tid & 31;
    int wm = wid >> 2, wn = wid & 3;
    int lq = lane >> 2, lr = lane & 3;
    int r0 = wm * 32, c0 = wn * 64;

    auto fill = [&](int kc, int buf){
        float* sW = sm + (buf ? SW1_OFF : SW0_OFF);
        float* sE = sm + (buf ? SE1_OFF : SE0_OFF);
        for (int q = tid; q < 4096; q += 512){
            int c = q >> 4, kk = (q & 15) * 4;
            *(float4*)(sW + c*SST + kk) = *(const float4*)(Wg + c*DM + kc*64 + kk);
        }
        for (int e = tid; e < 128*32; e += 512){
            int row = e >> 5, t2 = e & 31;
            float2 sc = egen(row, kc, t2);
            sE[row*SST + 2*t2]     = tfr(sc.x);
            sE[row*SST + 2*t2 + 1] = tfr(sc.y);
        }
    };

    fill(0, 0);
    __syncthreads();
    for (int kc = 0; kc < 4; kc++){
        if (kc < 3) fill(kc + 1, (kc + 1) & 1);
        const float* sE = sm + ((kc & 1) ? SE1_OFF : SE0_OFF);
        const float* sW = sm + ((kc & 1) ? SW1_OFF : SW0_OFF);
        #pragma unroll
        for (int k8 = 0; k8 < 8; k8++){
            int kk = k8 * 8;
            unsigned a[2][4];
            const float* pa = sE + (r0 + lq)*SST + kk + lr;
            #pragma unroll
            for (int mt = 0; mt < 2; mt++){
                const float* p = pa + mt*16*SST;
                a[mt][0] = __float_as_uint(p[0]);
                a[mt][1] = __float_as_uint(p[8*SST]);
                a[mt][2] = __float_as_uint(p[4]);
                a[mt][3] = __float_as_uint(p[8*SST + 4]);
            }
            #pragma unroll
            for (int nt = 0; nt < 8; nt++){
                unsigned b[2];
                const float* p = sW + (c0 + nt*8 + lq)*SST + kk + lr;
                b[0] = __float_as_uint(p[0]);
                b[1] = __float_as_uint(p[4]);
                mma8(acc[0][nt], a[0], b);
                mma8(acc[1][nt], a[1], b);
            }
        }
        __syncthreads();
    }
}

// ---- kernel: glo = (d_emb + a_ij_emb) @ W_d^T + 2 b_d ----
__global__ void __launch_bounds__(512, 1) glo_kernel(const float* __restrict__ nds,
                                                     const float* __restrict__ nn,
                                                     const float* __restrict__ bd,
                                                     float* __restrict__ out){
    extern __shared__ float sm[];
    float* sF = sm + SF_OFF;
    float* sT = sm + ST_OFF;
    int tid = threadIdx.x;
    int rowbase = blockIdx.x * 128;

    if (tid < 128) sT[tid] = exp2f(-(float)tid * 0.10381025296511650f);
    if (tid < 128){
        int gr = rowbase + tid;
        int i = gr >> 9, j = gr & 511;
        float ix = nds[3*i], iy = nds[3*i+1], iz = nds[3*i+2];
        float jx = nds[3*j], jy = nds[3*j+1], jz = nds[3*j+2];
        float dx = ix - jx, dy = iy - jy, dz = iz - jz;
        float dist = sqrtf(dx*dx + dy*dy + dz*dz) * TWO_PI;
        float ax = nn[3*i], ay = nn[3*i+1], az = nn[3*i+2];
        sF[2*tid]   = dist;
        // diagonal: reference's jnp.sum gives +0 dot -> arctan2(+0,+0)=0
        sF[2*tid+1] = (i == j) ? 0.0f : angle3(dx, dy, dz, ax, ay, az);
    }
    __syncthreads();

    float acc[2][8][4];
    #pragma unroll
    for (int mt = 0; mt < 2; mt++)
        #pragma unroll
        for (int nt = 0; nt < 8; nt++)
            #pragma unroll
            for (int q = 0; q < 4; q++) acc[mt][nt][q] = 0.f;

    gemm1(sm, g_Wd, acc, tid,
        [&](int row, int kc, int t2) -> float2 {
            float w = sT[kc*32 + t2];
            float d = sF[2*row], a = sF[2*row+1];
            float x1 = redang(d * w), x2 = redang(a * w);
            float s1 = __sinf(x1), c1 = __cosf(x1);
            float s2 = __sinf(x2), c2 = __cosf(x2);
            return make_float2(s1 + s2, c1 + c2);
        });

    int wid = tid >> 5, lane = tid & 31;
    int wm = wid >> 2, wn = wid & 3;
    int lq = lane >> 2, lr = lane & 3;
    #pragma unroll
    for (int mt = 0; mt < 2; mt++){
        #pragma unroll
        for (int nt = 0; nt < 8; nt++){
            int col = wn*64 + nt*8 + 2*lr;
            float b0 = 2.f * bd[col];
            float b1 = 2.f * bd[col+1];
            size_t r1 = (size_t)(rowbase + wm*32 + mt*16 + lq) * DM + col;
            size_t r2 = r1 + (size_t)8 * DM;
            float2 v1 = make_float2(acc[mt][nt][0] + b0, acc[mt][nt][1] + b1);
            float2 v2 = make_float2(acc[mt][nt][2] + b0, acc[mt][nt][3] + b1);
            *(float2*)(out + r1) = v1;
            *(float2*)(out + r2) = v2;
        }
    }
}

// ---- kernel: loc = max_k (a_patch @ W_patch^T) + b_patch ----
__global__ void __launch_bounds__(512, 1) loc_kernel(const float* __restrict__ pts,
                                                     const float* __restrict__ nds,
                                                     const float* __restrict__ pn,
                                                     const float* __restrict__ nn,
                                                     const float* __restrict__ bp,
                                                     float* __restrict__ out){
    extern __shared__ float sm[];
    float* sF = sm + SF_OFF;
    float* sT = sm + ST_OFF;
    float* sR = sm + SR_OFF;
    int tid = threadIdx.x;
    int m = blockIdx.x;

    if (tid < 32) sT[tid] = exp2f(-(float)tid * 0.41524101186046600f);
    if (tid < 128){
        int idx = g_knn[m*KNNK + tid];
        float cx = nds[3*m], cy = nds[3*m+1], cz = nds[3*m+2];
        float ax = nn[3*m],  ay = nn[3*m+1],  az = nn[3*m+2];
        float px = pts[3*idx], py = pts[3*idx+1], pz = pts[3*idx+2];
        float qx = pn[3*idx],  qy = pn[3*idx+1],  qz = pn[3*idx+2];
        float vx = px - cx, vy = py - cy, vz = pz - cz;
        sF[4*tid+0] = sqrtf(vx*vx + vy*vy + vz*vz) * TWO_PI;
        sF[4*tid+1] = angle3( vx,  vy,  vz, ax, ay, az);
        sF[4*tid+2] = angle3(-vx, -vy, -vz, qx, qy, qz);
        sF[4*tid+3] = angle3( ax,  ay,  az, qx, qy, qz);
    }
    __syncthreads();

    float acc[2][8][4];
    #pragma unroll
    for (int mt = 0; mt < 2; mt++)
        #pragma unroll
        for (int nt = 0; nt < 8; nt++)
            #pragma unroll
            for (int q = 0; q < 4; q++) acc[mt][nt][q] = 0.f;

    // each 64-wide k-chunk is exactly one quarter (kc = quarter index)
    gemm1(sm, g_Wp, acc, tid,
        [&](int row, int kc, int t2) -> float2 {
            float w = sT[t2];
            float s = sF[4*row + kc];
            float x = redang(s * w);
            return make_float2(__sinf(x), __cosf(x));
        });

    int wid = tid >> 5, lane = tid & 31;
    int wm = wid >> 2, wn = wid & 3;
    int lq = lane >> 2, lr = lane & 3;
    #pragma unroll
    for (int nt = 0; nt < 8; nt++){
        float em = fmaxf(fmaxf(acc[0][nt][0], acc[0][nt][2]),
                         fmaxf(acc[1][nt][0], acc[1][nt][2]));
        float om = fmaxf(fmaxf(acc[0][nt][1], acc[0][nt][3]),
                         fmaxf(acc[1][nt][1], acc[1][nt][3]));
        #pragma unroll
        for (int off = 4; off <= 16; off <<= 1){
            em = fmaxf(em, __shfl_xor_sync(0xffffffffu, em, off));
            om = fmaxf(om, __shfl_xor_sync(0xffffffffu, om, off));
        }
        if (lq == 0){
            sR[wm*256 + wn*64 + nt*8 + 2*lr]     = em;
            sR[wm*256 + wn*64 + nt*8 + 2*lr + 1] = om;
        }
    }
    __syncthreads();
    if (tid < 256){
        float mx = fmaxf(fmaxf(sR[tid], sR[256 + tid]),
                         fmaxf(sR[512 + tid], sR[768 + tid]));
        out[(size_t)MN*MN*DM + (size_t)m*DM + tid] = mx + bp[tid];
    }
}

extern "C" void kernel_launch(void* const* d_in, const int* in_sizes, int n_in,
                              void* d_out, int out_size){
    const float* pts   = (const float*)d_in[0];
    const float* nds   = (const float*)d_in[1];
    const float* pnorm = (const float*)d_in[2];
    const float* nnorm = (const float*)d_in[3];
    const float* Wd    = (const float*)d_in[4];
    const float* bd    = (const float*)d_in[5];
    const float* Wp    = (const float*)d_in[6];
    const float* bp    = (const float*)d_in[7];
    float* out = (float*)d_out;

    cudaFuncSetAttribute(glo_kernel, cudaFuncAttributeMaxDynamicSharedMemorySize, SMEM_BYTES);
    cudaFuncSetAttribute(loc_kernel, cudaFuncAttributeMaxDynamicSharedMemorySize, SMEM_BYTES);

    prep_kernel<<<(DM*DM + 255)/256, 256>>>(Wd, Wp);
    knn_kernel<<<MN, 256>>>(pts, nds);
    glo_kernel<<<(MN*MN)/128, 512, SMEM_BYTES>>>(nds, nnorm, bd, out);
    loc_kernel<<<MN, 512, SMEM_BYTES>>>(pts, nds, pnorm, nnorm, bp, out);
}

// round 15
// speedup vs baseline: 2.7292x; 1.0717x over previous
#include <cuda_runtime.h>
#include <cstdint>
#include <cstddef>

#define NPTS   16384
#define MN     512
#define DM     256
#define KNNK   128
#define TWO_PI 6.28318530717958647692f

__device__ float g_Wd[DM*DM];   // tf32-rounded
__device__ float g_Wp[DM*DM];   // tf32-rounded
__device__ int   g_knn[MN*KNNK];

static __device__ __forceinline__ unsigned f2tf(float x){
    unsigned u; asm("cvt.rna.tf32.f32 %0, %1;" : "=r"(u) : "f"(x)); return u;
}
static __device__ __forceinline__ float tfr(float x){ return __uint_as_float(f2tf(x)); }

// reduce to [-pi,pi] with 2-term 2*pi so MUFU sin/cos stays accurate
static __device__ __forceinline__ float redang(float x){
    float k = rintf(x * 0.15915494309189535f);
    float r = fmaf(k, -6.28318548202514648f, x);
    return fmaf(k, 1.74845560074738e-07f, r);
}
static __device__ __forceinline__ float angle3(float vx,float vy,float vz,
                                               float nx,float ny,float nz){
    float cx = vy*nz - vz*ny;
    float cy = vz*nx - vx*nz;
    float cz = vx*ny - vy*nx;
    float s  = sqrtf(cx*cx + cy*cy + cz*cz);
    float d  = vx*nx + vy*ny + vz*nz;
    return atan2f(s, d);
}
static __device__ __forceinline__ void mma8(float* c, const unsigned* a, const unsigned* b){
    asm volatile("mma.sync.aligned.m16n8k8.row.col.f32.tf32.tf32.f32 "
        "{%0,%1,%2,%3}, {%4,%5,%6,%7}, {%8,%9}, {%0,%1,%2,%3};"
        : "+f"(c[0]), "+f"(c[1]), "+f"(c[2]), "+f"(c[3])
        : "r"(a[0]), "r"(a[1]), "r"(a[2]), "r"(a[3]), "r"(b[0]), "r"(b[1]));
}

// ---- smem layout (floats); stride 68 (68%32==4 -> conflict-free frags) ----
#define SST 68
#define SE0_OFF 0
#define SE1_OFF (128*SST)
#define SW0_OFF (2*128*SST)
#define SW1_OFF (SW0_OFF + 256*SST)
#define SF_OFF  (SW0_OFF + 2*256*SST)
#define ST_OFF  (SF_OFF + 512)
#define SR_OFF  (ST_OFF + 128)
#define SMEM_FLOATS (SR_OFF + 1024)
#define SMEM_BYTES (SMEM_FLOATS * 4)   // 215552

__global__ void prep_kernel(const float* __restrict__ Wd, const float* __restrict__ Wp){
    int i = blockIdx.x * blockDim.x + threadIdx.x;
    if (i < DM*DM){
        g_Wd[i] = tfr(Wd[i]);
        g_Wp[i] = tfr(Wp[i]);
    }
}

__global__ void __launch_bounds__(256) knn_kernel(const float* __restrict__ pts,
                                                  const float* __restrict__ nds){
    int m = blockIdx.x, tid = threadIdx.x;
    __shared__ int scnt;
    __shared__ int pos;
    float nx = nds[3*m], ny = nds[3*m+1], nz = nds[3*m+2];
    float sqn = nx*nx + ny*ny + nz*nz;
    float v[64];
    #pragma unroll 4
    for (int s = 0; s < 64; s++){
        int i = s*256 + tid;
        float px = pts[3*i], py = pts[3*i+1], pz = pts[3*i+2];
        float sqp = px*px + py*py + pz*pz;
        float dot = nx*px + ny*py + nz*pz;
        v[s] = fmaxf((sqn + sqp) - 2.0f*dot, 0.f);
    }
    unsigned lo = 0u, hi = 0x7f800000u;
    while (lo < hi){
        unsigned mid = (lo + hi) >> 1;
        float fm = __uint_as_float(mid);
        if (tid == 0) scnt = 0;
        __syncthreads();
        int c = 0;
        #pragma unroll
        for (int s = 0; s < 64; s++) c += (v[s] <= fm) ? 1 : 0;
        c = (int)__reduce_add_sync(0xffffffffu, (unsigned)c);
        if ((tid & 31) == 0) atomicAdd(&scnt, c);
        __syncthreads();
        int total = scnt;
        __syncthreads();
        if (total >= KNNK) hi = mid; else lo = mid + 1;
    }
    float thr = __uint_as_float(lo);
    if (tid == 0) pos = 0;
    __syncthreads();
    for (int s = 0; s < 64; s++){
        if (v[s] < thr){
            int p = atomicAdd(&pos, 1);
            g_knn[m*KNNK + p] = s*256 + tid;
        }
    }
    __syncthreads();
    for (int s = 0; s < 64; s++){
        if (v[s] == thr){
            int p = atomicAdd(&pos, 1);
            if (p < KNNK) g_knn[m*KNNK + p] = s*256 + tid;
        }
    }
}

// ---- pure-TF32 GEMM, double-buffered W+E chunks, hoisted B fragments ----
template<class EGen>
static __device__ __forceinline__ void gemm1(float* sm,
                                             const float* __restrict__ Wg,
                                             float acc[2][8][4], int tid, EGen egen){
    int wid = tid >> 5, lane = tid & 31;
    int wm = wid >> 2, wn = wid & 3;
    int lq = lane >> 2, lr = lane & 3;
    int r0 = wm * 32, c0 = wn * 64;

    auto fill = [&](int kc, int buf){
        float* sW = sm + (buf ? SW1_OFF : SW0_OFF);
        float* sE = sm + (buf ? SE1_OFF : SE0_OFF);
        for (int q = tid; q < 4096; q += 512){
            int c = q >> 4, kk = (q & 15) * 4;
            *(float4*)(sW + c*SST + kk) = *(const float4*)(Wg + c*DM + kc*64 + kk);
        }
        for (int e = tid; e < 128*32; e += 512){
            int row = e >> 5, t2 = e & 31;
            float2 sc = egen(row, kc, t2);
            *(float2*)(sE + row*SST + 2*t2) = make_float2(tfr(sc.x), tfr(sc.y));
        }
    };

    fill(0, 0);
    __syncthreads();
    for (int kc = 0; kc < 4; kc++){
        if (kc < 3) fill(kc + 1, (kc + 1) & 1);
        const float* sE = sm + ((kc & 1) ? SE1_OFF : SE0_OFF);
        const float* sW = sm + ((kc & 1) ? SW1_OFF : SW0_OFF);
        #pragma unroll
        for (int k8 = 0; k8 < 8; k8++){
            int kk = k8 * 8;
            unsigned a[2][4];
            const float* pa = sE + (r0 + lq)*SST + kk + lr;
            #pragma unroll
            for (int mt = 0; mt < 2; mt++){
                const float* p = pa + mt*16*SST;
                a[mt][0] = __float_as_uint(p[0]);
                a[mt][1] = __float_as_uint(p[8*SST]);
                a[mt][2] = __float_as_uint(p[4]);
                a[mt][3] = __float_as_uint(p[8*SST + 4]);
            }
            unsigned b[8][2];
            #pragma unroll
            for (int nt = 0; nt < 8; nt++){
                const float* p = sW + (c0 + nt*8 + lq)*SST + kk + lr;
                b[nt][0] = __float_as_uint(p[0]);
                b[nt][1] = __float_as_uint(p[4]);
            }
            #pragma unroll
            for (int nt = 0; nt < 8; nt++){
                mma8(acc[0][nt], a[0], b[nt]);
                mma8(acc[1][nt], a[1], b[nt]);
            }
        }
        __syncthreads();
    }
}

// ---- kernel: glo = (d_emb + a_ij_emb) @ W_d^T + 2 b_d ----
__global__ void __launch_bounds__(512, 1) glo_kernel(const float* __restrict__ nds,
                                                     const float* __restrict__ nn,
                                                     const float* __restrict__ bd,
                                                     float* __restrict__ out){
    extern __shared__ float sm[];
    float* sF = sm + SF_OFF;
    float* sT = sm + ST_OFF;
    int tid = threadIdx.x;
    int rowbase = blockIdx.x * 128;

    if (tid < 128) sT[tid] = exp2f(-(float)tid * 0.10381025296511650f);
    if (tid < 128){
        int gr = rowbase + tid;
        int i = gr >> 9, j = gr & 511;
        float ix = nds[3*i], iy = nds[3*i+1], iz = nds[3*i+2];
        float jx = nds[3*j], jy = nds[3*j+1], jz = nds[3*j+2];
        float dx = ix - jx, dy = iy - jy, dz = iz - jz;
        float dist = sqrtf(dx*dx + dy*dy + dz*dz) * TWO_PI;
        float ax = nn[3*i], ay = nn[3*i+1], az = nn[3*i+2];
        sF[2*tid]   = dist;
        // diagonal: reference's jnp.sum gives +0 dot -> arctan2(+0,+0)=0
        sF[2*tid+1] = (i == j) ? 0.0f : angle3(dx, dy, dz, ax, ay, az);
    }
    __syncthreads();

    float acc[2][8][4];
    #pragma unroll
    for (int mt = 0; mt < 2; mt++)
        #pragma unroll
        for (int nt = 0; nt < 8; nt++)
            #pragma unroll
            for (int q = 0; q < 4; q++) acc[mt][nt][q] = 0.f;

    gemm1(sm, g_Wd, acc, tid,
        [&](int row, int kc, int t2) -> float2 {
            float w = sT[kc*32 + t2];
            float d = sF[2*row], a = sF[2*row+1];
            float x1 = redang(d * w), x2 = redang(a * w);
            float s1 = __sinf(x1), c1 = __cosf(x1);
            float s2 = __sinf(x2), c2 = __cosf(x2);
            return make_float2(s1 + s2, c1 + c2);
        });

    int wid = tid >> 5, lane = tid & 31;
    int wm = wid >> 2, wn = wid & 3;
    int lq = lane >> 2, lr = lane & 3;
    #pragma unroll
    for (int mt = 0; mt < 2; mt++){
        #pragma unroll
        for (int nt = 0; nt < 8; nt++){
            int col = wn*64 + nt*8 + 2*lr;
            float b0 = 2.f * bd[col];
            float b1 = 2.f * bd[col+1];
            size_t r1 = (size_t)(rowbase + wm*32 + mt*16 + lq) * DM + col;
            size_t r2 = r1 + (size_t)8 * DM;
            float2 v1 = make_float2(acc[mt][nt][0] + b0, acc[mt][nt][1] + b1);
            float2 v2 = make_float2(acc[mt][nt][2] + b0, acc[mt][nt][3] + b1);
            *(float2*)(out + r1) = v1;
            *(float2*)(out + r2) = v2;
        }
    }
}

// ---- kernel: loc = max_k (a_patch @ W_patch^T) + b_patch ----
__global__ void __launch_bounds__(512, 1) loc_kernel(const float* __restrict__ pts,
                                                     const float* __restrict__ nds,
                                                     const float* __restrict__ pn,
                                                     const float* __restrict__ nn,
                                                     const float* __restrict__ bp,
                                                     float* __restrict__ out){
    extern __shared__ float sm[];
    float* sF = sm + SF_OFF;
    float* sT = sm + ST_OFF;
    float* sR = sm + SR_OFF;
    int tid = threadIdx.x;
    int m = blockIdx.x;

    if (tid < 32) sT[tid] = exp2f(-(float)tid * 0.41524101186046600f);
    if (tid < 128){
        int idx = g_knn[m*KNNK + tid];
        float cx = nds[3*m], cy = nds[3*m+1], cz = nds[3*m+2];
        float ax = nn[3*m],  ay = nn[3*m+1],  az = nn[3*m+2];
        float px = pts[3*idx], py = pts[3*idx+1], pz = pts[3*idx+2];
        float qx = pn[3*idx],  qy = pn[3*idx+1],  qz = pn[3*idx+2];
        float vx = px - cx, vy = py - cy, vz = pz - cz;
        sF[4*tid+0] = sqrtf(vx*vx + vy*vy + vz*vz) * TWO_PI;
        sF[4*tid+1] = angle3( vx,  vy,  vz, ax, ay, az);
        sF[4*tid+2] = angle3(-vx, -vy, -vz, qx, qy, qz);
        sF[4*tid+3] = angle3( ax,  ay,  az, qx, qy, qz);
    }
    __syncthreads();

    float acc[2][8][4];
    #pragma unroll
    for (int mt = 0; mt < 2; mt++)
        #pragma unroll
        for (int nt = 0; nt < 8; nt++)
            #pragma unroll
            for (int q = 0; q < 4; q++) acc[mt][nt][q] = 0.f;

    gemm1(sm, g_Wp, acc, tid,
        [&](int row, int kc, int t2) -> float2 {
            float w = sT[t2];
            float s = sF[4*row + kc];
            float x = redang(s * w);
            return make_float2(__sinf(x), __cosf(x));
        });

    int wid = tid >> 5, lane = tid & 31;
    int wm = wid >> 2, wn = wid & 3;
    int lq = lane >> 2, lr = lane & 3;
    #pragma unroll
    for (int nt = 0; nt < 8; nt++){
        float em = fmaxf(fmaxf(acc[0][nt][0], acc[0][nt][2]),
                         fmaxf(acc[1][nt][0], acc[1][nt][2]));
        float om = fmaxf(fmaxf(acc[0][nt][1], acc[0][nt][3]),
                         fmaxf(acc[1][nt][1], acc[1][nt][3]));
        #pragma unroll
        for (int off = 4; off <= 16; off <<= 1){
            em = fmaxf(em, __shfl_xor_sync(0xffffffffu, em, off));
            om = fmaxf(om, __shfl_xor_sync(0xffffffffu, om, off));
        }
        if (lq == 0){
            sR[wm*256 + wn*64 + nt*8 + 2*lr]     = em;
            sR[wm*256 + wn*64 + nt*8 + 2*lr + 1] = om;
        }
    }
    __syncthreads();
    if (tid < 256){
        float mx = fmaxf(fmaxf(sR[tid], sR[256 + tid]),
                         fmaxf(sR[512 + tid], sR[768 + tid]));
        out[(size_t)MN*MN*DM + (size_t)m*DM + tid] = mx + bp[tid];
    }
}

// ---- launch: prep -> fork { glo } || { knn -> loc } -> join ----
extern "C" void kernel_launch(void* const* d_in, const int* in_sizes, int n_in,
                              void* d_out, int out_size){
    const float* pts   = (const float*)d_in[0];
    const float* nds   = (const float*)d_in[1];
    const float* pnorm = (const float*)d_in[2];
    const float* nnorm = (const float*)d_in[3];
    const float* Wd    = (const float*)d_in[4];
    const float* bd    = (const float*)d_in[5];
    const float* Wp    = (const float*)d_in[6];
    const float* bp    = (const float*)d_in[7];
    float* out = (float*)d_out;

    cudaFuncSetAttribute(glo_kernel, cudaFuncAttributeMaxDynamicSharedMemorySize, SMEM_BYTES);
    cudaFuncSetAttribute(loc_kernel, cudaFuncAttributeMaxDynamicSharedMemorySize, SMEM_BYTES);

    // Side stream + events created per call and intentionally not destroyed:
    // kernel_launch runs only a couple of times (correctness + capture) and
    // destroying them mid-capture would invalidate the graph. Non-blocking
    // stream avoids legacy-NULL-stream implicit serialization.
    cudaStream_t s2;
    cudaStreamCreateWithFlags(&s2, cudaStreamNonBlocking);
    cudaEvent_t eFork, eJoin;
    cudaEventCreateWithFlags(&eFork, cudaEventDisableTiming);
    cudaEventCreateWithFlags(&eJoin, cudaEventDisableTiming);

    prep_kernel<<<(DM*DM + 255)/256, 256>>>(Wd, Wp);
    cudaEventRecord(eFork, 0);
    cudaStreamWaitEvent(s2, eFork, 0);

    // side chain: knn -> loc (independent of glo)
    knn_kernel<<<MN, 256, 0, s2>>>(pts, nds);
    loc_kernel<<<MN, 512, SMEM_BYTES, s2>>>(pts, nds, pnorm, nnorm, bp, out);

    // main chain: glo (the big one), overlapped with the side chain
    glo_kernel<<<(MN*MN)/128, 512, SMEM_BYTES>>>(nds, nnorm, bd, out);

    cudaEventRecord(eJoin, s2);
    cudaStreamWaitEvent(0, eJoin, 0);
}

// round 16
// speedup vs baseline: 2.7894x; 1.0220x over previous
#include <cuda_runtime.h>
#include <cstdint>
#include <cstddef>

#define NPTS   16384
#define MN     512
#define DM     256
#define KNNK   128
#define TWO_PI 6.28318530717958647692f

__device__ float g_Wd[DM*DM];   // tf32-rounded
__device__ float g_Wp[DM*DM];   // tf32-rounded
__device__ int   g_knn[MN*KNNK];

static __device__ __forceinline__ unsigned f2tf(float x){
    unsigned u; asm("cvt.rna.tf32.f32 %0, %1;" : "=r"(u) : "f"(x)); return u;
}
static __device__ __forceinline__ float tfr(float x){ return __uint_as_float(f2tf(x)); }

// reduce to [-pi,pi] with 2-term 2*pi so MUFU sin/cos stays accurate
static __device__ __forceinline__ float redang(float x){
    float k = rintf(x * 0.15915494309189535f);
    float r = fmaf(k, -6.28318548202514648f, x);
    return fmaf(k, 1.74845560074738e-07f, r);
}
static __device__ __forceinline__ float angle3(float vx,float vy,float vz,
                                               float nx,float ny,float nz){
    float cx = vy*nz - vz*ny;
    float cy = vz*nx - vx*nz;
    float cz = vx*ny - vy*nx;
    float s  = sqrtf(cx*cx + cy*cy + cz*cz);
    float d  = vx*nx + vy*ny + vz*nz;
    return atan2f(s, d);
}
static __device__ __forceinline__ void mma8(float* c, const unsigned* a, const unsigned* b){
    asm volatile("mma.sync.aligned.m16n8k8.row.col.f32.tf32.tf32.f32 "
        "{%0,%1,%2,%3}, {%4,%5,%6,%7}, {%8,%9}, {%0,%1,%2,%3};"
        : "+f"(c[0]), "+f"(c[1]), "+f"(c[2]), "+f"(c[3])
        : "r"(a[0]), "r"(a[1]), "r"(a[2]), "r"(a[3]), "r"(b[0]), "r"(b[1]));
}

// ---- glo smem layout: 64x256 tile, 256 threads, single-buffered ----
#define GST 68
#define GW_OFF 0                      // W chunk 256x68
#define GE_OFF (256*GST)              // 17408: E chunk 64x68
#define GF_OFF (GE_OFF + 64*GST)      // 21760: 128 feature floats
#define GT_OFF (GF_OFF + 128)         // 21888: 128 omega floats
#define G_FLOATS (GT_OFF + 128)       // 22016
#define G_BYTES (G_FLOATS * 4)        // 88064

// ---- loc smem layout (unchanged 512-thread version, double-buffered) ----
#define SST 68
#define SE0_OFF 0
#define SE1_OFF (128*SST)
#define SW0_OFF (2*128*SST)
#define SW1_OFF (SW0_OFF + 256*SST)
#define SF_OFF  (SW0_OFF + 2*256*SST)
#define ST_OFF  (SF_OFF + 512)
#define SR_OFF  (ST_OFF + 128)
#define SMEM_FLOATS (SR_OFF + 1024)
#define SMEM_BYTES (SMEM_FLOATS * 4)   // 215552

__global__ void prep_kernel(const float* __restrict__ Wd, const float* __restrict__ Wp){
    int i = blockIdx.x * blockDim.x + threadIdx.x;
    if (i < DM*DM){
        g_Wd[i] = tfr(Wd[i]);
        g_Wp[i] = tfr(Wp[i]);
    }
}

__global__ void __launch_bounds__(256) knn_kernel(const float* __restrict__ pts,
                                                  const float* __restrict__ nds){
    int m = blockIdx.x, tid = threadIdx.x;
    __shared__ int scnt;
    __shared__ int pos;
    float nx = nds[3*m], ny = nds[3*m+1], nz = nds[3*m+2];
    float sqn = nx*nx + ny*ny + nz*nz;
    float v[64];
    #pragma unroll 4
    for (int s = 0; s < 64; s++){
        int i = s*256 + tid;
        float px = pts[3*i], py = pts[3*i+1], pz = pts[3*i+2];
        float sqp = px*px + py*py + pz*pz;
        float dot = nx*px + ny*py + nz*pz;
        v[s] = fmaxf((sqn + sqp) - 2.0f*dot, 0.f);
    }
    unsigned lo = 0u, hi = 0x7f800000u;
    while (lo < hi){
        unsigned mid = (lo + hi) >> 1;
        float fm = __uint_as_float(mid);
        if (tid == 0) scnt = 0;
        __syncthreads();
        int c = 0;
        #pragma unroll
        for (int s = 0; s < 64; s++) c += (v[s] <= fm) ? 1 : 0;
        c = (int)__reduce_add_sync(0xffffffffu, (unsigned)c);
        if ((tid & 31) == 0) atomicAdd(&scnt, c);
        __syncthreads();
        int total = scnt;
        __syncthreads();
        if (total >= KNNK) hi = mid; else lo = mid + 1;
    }
    float thr = __uint_as_float(lo);
    if (tid == 0) pos = 0;
    __syncthreads();
    for (int s = 0; s < 64; s++){
        if (v[s] < thr){
            int p = atomicAdd(&pos, 1);
            g_knn[m*KNNK + p] = s*256 + tid;
        }
    }
    __syncthreads();
    for (int s = 0; s < 64; s++){
        if (v[s] == thr){
            int p = atomicAdd(&pos, 1);
            if (p < KNNK) g_knn[m*KNNK + p] = s*256 + tid;
        }
    }
}

// ---- glo: 64x256 tile, 256 threads, 2 CTAs/SM ----
__global__ void __launch_bounds__(256, 2) glo_kernel(const float* __restrict__ nds,
                                                     const float* __restrict__ nn,
                                                     const float* __restrict__ bd,
                                                     float* __restrict__ out){
    extern __shared__ float sm[];
    float* sW = sm + GW_OFF;
    float* sE = sm + GE_OFF;
    float* sF = sm + GF_OFF;
    float* sT = sm + GT_OFF;
    int tid = threadIdx.x;
    int rowbase = blockIdx.x * 64;

    if (tid < 128) sT[tid] = exp2f(-(float)tid * 0.10381025296511650f);
    if (tid < 64){
        int gr = rowbase + tid;
        int i = gr >> 9, j = gr & 511;
        float ix = nds[3*i], iy = nds[3*i+1], iz = nds[3*i+2];
        float jx = nds[3*j], jy = nds[3*j+1], jz = nds[3*j+2];
        float dx = ix - jx, dy = iy - jy, dz = iz - jz;
        float dist = sqrtf(dx*dx + dy*dy + dz*dz) * TWO_PI;
        float ax = nn[3*i], ay = nn[3*i+1], az = nn[3*i+2];
        sF[2*tid]   = dist;
        // diagonal: reference's jnp.sum gives +0 dot -> arctan2(+0,+0)=0
        sF[2*tid+1] = (i == j) ? 0.0f : angle3(dx, dy, dz, ax, ay, az);
    }
    __syncthreads();

    float acc[2][8][4];
    #pragma unroll
    for (int mt = 0; mt < 2; mt++)
        #pragma unroll
        for (int nt = 0; nt < 8; nt++)
            #pragma unroll
            for (int q = 0; q < 4; q++) acc[mt][nt][q] = 0.f;

    int wid = tid >> 5, lane = tid & 31;
    int wm = wid >> 2, wn = wid & 3;       // wm: 2x32 rows, wn: 4x64 cols
    int lq = lane >> 2, lr = lane & 3;
    int r0 = wm * 32, c0 = wn * 64;

    for (int kc = 0; kc < 4; kc++){
        if (kc) __syncthreads();           // all reads of prev chunk done
        // W chunk: all 256 out-cols x 64 k
        for (int q = tid; q < 4096; q += 256){
            int c = q >> 4, kk = (q & 15) * 4;
            *(float4*)(sW + c*GST + kk) = *(const float4*)(g_Wd + c*DM + kc*64 + kk);
        }
        // E chunk: 64 rows x 64 k (32 sin/cos pairs)
        for (int e = tid; e < 64*32; e += 256){
            int row = e >> 5, t2 = e & 31;
            float w = sT[kc*32 + t2];
            float d = sF[2*row], a = sF[2*row+1];
            float x1 = redang(d * w), x2 = redang(a * w);
            float s1 = __sinf(x1), c1 = __cosf(x1);
            float s2 = __sinf(x2), c2 = __cosf(x2);
            *(float2*)(sE + row*GST + 2*t2) = make_float2(tfr(s1 + s2), tfr(c1 + c2));
        }
        __syncthreads();
        #pragma unroll
        for (int k8 = 0; k8 < 8; k8++){
            int kk = k8 * 8;
            unsigned a[2][4];
            const float* pa = sE + (r0 + lq)*GST + kk + lr;
            #pragma unroll
            for (int mt = 0; mt < 2; mt++){
                const float* p = pa + mt*16*GST;
                a[mt][0] = __float_as_uint(p[0]);
                a[mt][1] = __float_as_uint(p[8*GST]);
                a[mt][2] = __float_as_uint(p[4]);
                a[mt][3] = __float_as_uint(p[8*GST + 4]);
            }
            unsigned b[8][2];
            #pragma unroll
            for (int nt = 0; nt < 8; nt++){
                const float* p = sW + (c0 + nt*8 + lq)*GST + kk + lr;
                b[nt][0] = __float_as_uint(p[0]);
                b[nt][1] = __float_as_uint(p[4]);
            }
            #pragma unroll
            for (int nt = 0; nt < 8; nt++){
                mma8(acc[0][nt], a[0], b[nt]);
                mma8(acc[1][nt], a[1], b[nt]);
            }
        }
    }

    #pragma unroll
    for (int mt = 0; mt < 2; mt++){
        #pragma unroll
        for (int nt = 0; nt < 8; nt++){
            int col = wn*64 + nt*8 + 2*lr;
            float b0 = 2.f * bd[col];
            float b1 = 2.f * bd[col+1];
            size_t r1 = (size_t)(rowbase + wm*32 + mt*16 + lq) * DM + col;
            size_t r2 = r1 + (size_t)8 * DM;
            *(float2*)(out + r1) = make_float2(acc[mt][nt][0] + b0, acc[mt][nt][1] + b1);
            *(float2*)(out + r2) = make_float2(acc[mt][nt][2] + b0, acc[mt][nt][3] + b1);
        }
    }
}

// ---- loc: unchanged 512-thread double-buffered version ----
template<class EGen>
static __device__ __forceinline__ void gemm1(float* sm,
                                             const float* __restrict__ Wg,
                                             float acc[2][8][4], int tid, EGen egen){
    int wid = tid >> 5, lane = tid & 31;
    int wm = wid >> 2, wn = wid & 3;
    int lq = lane >> 2, lr = lane & 3;
    int r0 = wm * 32, c0 = wn * 64;

    auto fill = [&](int kc, int buf){
        float* sW = sm + (buf ? SW1_OFF : SW0_OFF);
        float* sE = sm + (buf ? SE1_OFF : SE0_OFF);
        for (int q = tid; q < 4096; q += 512){
            int c = q >> 4, kk = (q & 15) * 4;
            *(float4*)(sW + c*SST + kk) = *(const float4*)(Wg + c*DM + kc*64 + kk);
        }
        for (int e = tid; e < 128*32; e += 512){
            int row = e >> 5, t2 = e & 31;
            float2 sc = egen(row, kc, t2);
            *(float2*)(sE + row*SST + 2*t2) = make_float2(tfr(sc.x), tfr(sc.y));
        }
    };

    fill(0, 0);
    __syncthreads();
    for (int kc = 0; kc < 4; kc++){
        if (kc < 3) fill(kc + 1, (kc + 1) & 1);
        const float* sE = sm + ((kc & 1) ? SE1_OFF : SE0_OFF);
        const float* sW = sm + ((kc & 1) ? SW1_OFF : SW0_OFF);
        #pragma unroll
        for (int k8 = 0; k8 < 8; k8++){
            int kk = k8 * 8;
            unsigned a[2][4];
            const float* pa = sE + (r0 + lq)*SST + kk + lr;
            #pragma unroll
            for (int mt = 0; mt < 2; mt++){
                const float* p = pa + mt*16*SST;
                a[mt][0] = __float_as_uint(p[0]);
                a[mt][1] = __float_as_uint(p[8*SST]);
                a[mt][2] = __float_as_uint(p[4]);
                a[mt][3] = __float_as_uint(p[8*SST + 4]);
            }
            unsigned b[8][2];
            #pragma unroll
            for (int nt = 0; nt < 8; nt++){
                const float* p = sW + (c0 + nt*8 + lq)*SST + kk + lr;
                b[nt][0] = __float_as_uint(p[0]);
                b[nt][1] = __float_as_uint(p[4]);
            }
            #pragma unroll
            for (int nt = 0; nt < 8; nt++){
                mma8(acc[0][nt], a[0], b[nt]);
                mma8(acc[1][nt], a[1], b[nt]);
            }
        }
        __syncthreads();
    }
}

__global__ void __launch_bounds__(512, 1) loc_kernel(const float* __restrict__ pts,
                                                     const float* __restrict__ nds,
                                                     const float* __restrict__ pn,
                                                     const float* __restrict__ nn,
                                                     const float* __restrict__ bp,
                                                     float* __restrict__ out){
    extern __shared__ float sm[];
    float* sF = sm + SF_OFF;
    float* sT = sm + ST_OFF;
    float* sR = sm + SR_OFF;
    int tid = threadIdx.x;
    int m = blockIdx.x;

    if (tid < 32) sT[tid] = exp2f(-(float)tid * 0.41524101186046600f);
    if (tid < 128){
        int idx = g_knn[m*KNNK + tid];
        float cx = nds[3*m], cy = nds[3*m+1], cz = nds[3*m+2];
        float ax = nn[3*m],  ay = nn[3*m+1],  az = nn[3*m+2];
        float px = pts[3*idx], py = pts[3*idx+1], pz = pts[3*idx+2];
        float qx = pn[3*idx],  qy = pn[3*idx+1],  qz = pn[3*idx+2];
        float vx = px - cx, vy = py - cy, vz = pz - cz;
        sF[4*tid+0] = sqrtf(vx*vx + vy*vy + vz*vz) * TWO_PI;
        sF[4*tid+1] = angle3( vx,  vy,  vz, ax, ay, az);
        sF[4*tid+2] = angle3(-vx, -vy, -vz, qx, qy, qz);
        sF[4*tid+3] = angle3( ax,  ay,  az, qx, qy, qz);
    }
    __syncthreads();

    float acc[2][8][4];
    #pragma unroll
    for (int mt = 0; mt < 2; mt++)
        #pragma unroll
        for (int nt = 0; nt < 8; nt++)
            #pragma unroll
            for (int q = 0; q < 4; q++) acc[mt][nt][q] = 0.f;

    gemm1(sm, g_Wp, acc, tid,
        [&](int row, int kc, int t2) -> float2 {
            float w = sT[t2];
            float s = sF[4*row + kc];
            float x = redang(s * w);
            return make_float2(__sinf(x), __cosf(x));
        });

    int wid = tid >> 5, lane = tid & 31;
    int wm = wid >> 2, wn = wid & 3;
    int lq = lane >> 2, lr = lane & 3;
    #pragma unroll
    for (int nt = 0; nt < 8; nt++){
        float em = fmaxf(fmaxf(acc[0][nt][0], acc[0][nt][2]),
                         fmaxf(acc[1][nt][0], acc[1][nt][2]));
        float om = fmaxf(fmaxf(acc[0][nt][1], acc[0][nt][3]),
                         fmaxf(acc[1][nt][1], acc[1][nt][3]));
        #pragma unroll
        for (int off = 4; off <= 16; off <<= 1){
            em = fmaxf(em, __shfl_xor_sync(0xffffffffu, em, off));
            om = fmaxf(om, __shfl_xor_sync(0xffffffffu, om, off));
        }
        if (lq == 0){
            sR[wm*256 + wn*64 + nt*8 + 2*lr]     = em;
            sR[wm*256 + wn*64 + nt*8 + 2*lr + 1] = om;
        }
    }
    __syncthreads();
    if (tid < 256){
        float mx = fmaxf(fmaxf(sR[tid], sR[256 + tid]),
                         fmaxf(sR[512 + tid], sR[768 + tid]));
        out[(size_t)MN*MN*DM + (size_t)m*DM + tid] = mx + bp[tid];
    }
}

// ---- launch: prep -> fork { glo } || { knn -> loc } -> join ----
extern "C" void kernel_launch(void* const* d_in, const int* in_sizes, int n_in,
                              void* d_out, int out_size){
    const float* pts   = (const float*)d_in[0];
    const float* nds   = (const float*)d_in[1];
    const float* pnorm = (const float*)d_in[2];
    const float* nnorm = (const float*)d_in[3];
    const float* Wd    = (const float*)d_in[4];
    const float* bd    = (const float*)d_in[5];
    const float* Wp    = (const float*)d_in[6];
    const float* bp    = (const float*)d_in[7];
    float* out = (float*)d_out;

    cudaFuncSetAttribute(glo_kernel, cudaFuncAttributeMaxDynamicSharedMemorySize, G_BYTES);
    cudaFuncSetAttribute(loc_kernel, cudaFuncAttributeMaxDynamicSharedMemorySize, SMEM_BYTES);

    // Side stream + events intentionally not destroyed (graph capture safety).
    cudaStream_t s2;
    cudaStreamCreateWithFlags(&s2, cudaStreamNonBlocking);
    cudaEvent_t eFork, eJoin;
    cudaEventCreateWithFlags(&eFork, cudaEventDisableTiming);
    cudaEventCreateWithFlags(&eJoin, cudaEventDisableTiming);

    prep_kernel<<<(DM*DM + 255)/256, 256>>>(Wd, Wp);
    cudaEventRecord(eFork, 0);
    cudaStreamWaitEvent(s2, eFork, 0);

    knn_kernel<<<MN, 256, 0, s2>>>(pts, nds);
    loc_kernel<<<MN, 512, SMEM_BYTES, s2>>>(pts, nds, pnorm, nnorm, bp, out);

    glo_kernel<<<(MN*MN)/64, 256, G_BYTES>>>(nds, nnorm, bd, out);

    cudaEventRecord(eJoin, s2);
    cudaStreamWaitEvent(0, eJoin, 0);
}